// round 1
// baseline (speedup 1.0000x reference)
#include <cuda_runtime.h>
#include <cuda_bf16.h>

#define D_MODEL 1024
#define NUM_HEADS 16
#define DEPTH 64
#define BATCH 2
#define SEQ 2048
#define MROWS (BATCH * SEQ)   // 4096

// Scratch (no allocations allowed)
__device__ float g_Q[MROWS * D_MODEL];
__device__ float g_K[MROWS * D_MODEL];
__device__ float g_V[MROWS * D_MODEL];
__device__ float g_O[MROWS * D_MODEL];

// ---------------------------------------------------------------------------
// SGEMM: C[M,N] = A[M,K] @ B[K,N] + bias[N]
// M=4096, N=K=1024. 128x128x8 tile, 256 threads, 8x8 per-thread micro-tile.
// ---------------------------------------------------------------------------
__global__ __launch_bounds__(256, 2)
void sgemm_bias(const float* __restrict__ A, const float* __restrict__ Bm,
                const float* __restrict__ bias, float* __restrict__ C) {
    const int N = 1024, K = 1024;
    const int BM = 128, BN = 128, BK = 8;
    __shared__ float As[BK][BM];
    __shared__ float Bs[BK][BN];

    int tid = threadIdx.x;
    int tx = tid & 15;        // 0..15  (N direction)
    int ty = tid >> 4;        // 0..15  (M direction)
    int row0 = blockIdx.y * BM;
    int col0 = blockIdx.x * BN;

    float acc[8][8];
#pragma unroll
    for (int i = 0; i < 8; i++)
#pragma unroll
        for (int j = 0; j < 8; j++) acc[i][j] = 0.f;

    int arow = tid >> 1;           // 0..127
    int acol = (tid & 1) * 4;      // 0 or 4
    int brow = tid >> 5;           // 0..7
    int bcol = (tid & 31) * 4;     // 0..124

    const float* Ap = A + (size_t)(row0 + arow) * K + acol;
    const float* Bp = Bm + (size_t)brow * N + col0 + bcol;

    for (int k0 = 0; k0 < K; k0 += BK) {
        float4 a4 = *(const float4*)(Ap + k0);
        As[acol + 0][arow] = a4.x;
        As[acol + 1][arow] = a4.y;
        As[acol + 2][arow] = a4.z;
        As[acol + 3][arow] = a4.w;
        float4 b4 = *(const float4*)(Bp + (size_t)k0 * N);
        *(float4*)(&Bs[brow][bcol]) = b4;
        __syncthreads();

#pragma unroll
        for (int kk = 0; kk < BK; kk++) {
            float4 a0 = *(const float4*)(&As[kk][ty * 4]);
            float4 a1 = *(const float4*)(&As[kk][64 + ty * 4]);
            float4 b0 = *(const float4*)(&Bs[kk][tx * 4]);
            float4 b1 = *(const float4*)(&Bs[kk][64 + tx * 4]);
            float ar[8] = {a0.x, a0.y, a0.z, a0.w, a1.x, a1.y, a1.z, a1.w};
            float br[8] = {b0.x, b0.y, b0.z, b0.w, b1.x, b1.y, b1.z, b1.w};
#pragma unroll
            for (int i = 0; i < 8; i++)
#pragma unroll
                for (int j = 0; j < 8; j++)
                    acc[i][j] += ar[i] * br[j];
        }
        __syncthreads();
    }

#pragma unroll
    for (int ih = 0; ih < 2; ih++) {
#pragma unroll
        for (int i = 0; i < 4; i++) {
            int r = row0 + ih * 64 + ty * 4 + i;
#pragma unroll
            for (int jh = 0; jh < 2; jh++) {
                int c = col0 + jh * 64 + tx * 4;
                float4 bv = *(const float4*)(bias + c);
                float4 o;
                o.x = acc[ih * 4 + i][jh * 4 + 0] + bv.x;
                o.y = acc[ih * 4 + i][jh * 4 + 1] + bv.y;
                o.z = acc[ih * 4 + i][jh * 4 + 2] + bv.z;
                o.w = acc[ih * 4 + i][jh * 4 + 3] + bv.w;
                *(float4*)(C + (size_t)r * N + c) = o;
            }
        }
    }
}

// ---------------------------------------------------------------------------
// Flash attention (causal), fp32. One thread = one query row.
// Block: 128 threads = 128 queries of one (b,h). K/V staged in 64x64 SMEM tiles.
// Q,K,V,O layouts: [B, S, D_MODEL], head h occupies columns [h*64, h*64+64).
// ---------------------------------------------------------------------------
__global__ __launch_bounds__(128)
void flash_attn(const float* __restrict__ Q, const float* __restrict__ K,
                const float* __restrict__ V, float* __restrict__ O) {
    __shared__ float Ks[64][64];
    __shared__ float Vs[64][64];

    int qt = blockIdx.x;   // 0..15 (query tile of 128)
    int h  = blockIdx.y;   // 0..15
    int b  = blockIdx.z;   // 0..1
    int tid = threadIdx.x;
    int qi = qt * 128 + tid;

    const float* qptr = Q + ((size_t)b * SEQ + qi) * D_MODEL + h * DEPTH;
    float qreg[DEPTH];
#pragma unroll
    for (int d = 0; d < DEPTH; d += 4) {
        float4 t = *(const float4*)(qptr + d);
        qreg[d] = t.x; qreg[d + 1] = t.y; qreg[d + 2] = t.z; qreg[d + 3] = t.w;
    }

    float m = -1e30f, l = 0.f;
    float acc[DEPTH];
#pragma unroll
    for (int d = 0; d < DEPTH; d++) acc[d] = 0.f;

    int ktiles = qt * 2 + 2;  // tiles of 64 keys covering [0, qt*128+128)
    for (int kt = 0; kt < ktiles; kt++) {
        const float* kbase = K + ((size_t)b * SEQ + kt * 64) * D_MODEL + h * DEPTH;
        const float* vbase = V + ((size_t)b * SEQ + kt * 64) * D_MODEL + h * DEPTH;
#pragma unroll
        for (int it = 0; it < 8; it++) {
            int idx = (it * 128 + tid) * 4;  // float offset within 64x64 tile
            int r = idx >> 6;
            int c = idx & 63;
            *(float4*)(&Ks[r][c]) = *(const float4*)(kbase + (size_t)r * D_MODEL + c);
            *(float4*)(&Vs[r][c]) = *(const float4*)(vbase + (size_t)r * D_MODEL + c);
        }
        __syncthreads();

        int kmax = qi - kt * 64 + 1;       // causal bound within this tile
        if (kmax > 64) kmax = 64;
        for (int kk = 0; kk < kmax; kk++) {
            float s = 0.f;
#pragma unroll
            for (int d = 0; d < DEPTH; d++) s += qreg[d] * Ks[kk][d];
            s *= 0.125f;                    // 1/sqrt(64)
            if (s > m) {                    // lazy rescale
                float corr = __expf(m - s);
                l *= corr;
#pragma unroll
                for (int d = 0; d < DEPTH; d++) acc[d] *= corr;
                m = s;
            }
            float p = __expf(s - m);
            l += p;
#pragma unroll
            for (int d = 0; d < DEPTH; d++) acc[d] += p * Vs[kk][d];
        }
        __syncthreads();
    }

    float inv = 1.f / l;
    float* optr = O + ((size_t)b * SEQ + qi) * D_MODEL + h * DEPTH;
#pragma unroll
    for (int d = 0; d < DEPTH; d += 4) {
        float4 o;
        o.x = acc[d] * inv; o.y = acc[d + 1] * inv;
        o.z = acc[d + 2] * inv; o.w = acc[d + 3] * inv;
        *(float4*)(optr + d) = o;
    }
}

// ---------------------------------------------------------------------------
// Launch
// ---------------------------------------------------------------------------
extern "C" void kernel_launch(void* const* d_in, const int* in_sizes, int n_in,
                              void* d_out, int out_size) {
    const float* v  = (const float*)d_in[0];
    const float* k  = (const float*)d_in[1];
    const float* q  = (const float*)d_in[2];
    // d_in[3] = mask: fixed causal triu * (-1e9); handled analytically.
    const float* Wq = (const float*)d_in[4];
    const float* bq = (const float*)d_in[5];
    const float* Wk = (const float*)d_in[6];
    const float* bk = (const float*)d_in[7];
    const float* Wv = (const float*)d_in[8];
    const float* bv = (const float*)d_in[9];
    const float* Wo = (const float*)d_in[10];
    const float* bo = (const float*)d_in[11];

    float *gQ, *gK, *gV, *gO;
    cudaGetSymbolAddress((void**)&gQ, g_Q);
    cudaGetSymbolAddress((void**)&gK, g_K);
    cudaGetSymbolAddress((void**)&gV, g_V);
    cudaGetSymbolAddress((void**)&gO, g_O);

    dim3 ggrid(D_MODEL / 128, MROWS / 128);  // (8, 32)
    dim3 gblock(256);

    sgemm_bias<<<ggrid, gblock>>>(q, Wq, bq, gQ);
    sgemm_bias<<<ggrid, gblock>>>(k, Wk, bk, gK);
    sgemm_bias<<<ggrid, gblock>>>(v, Wv, bv, gV);

    dim3 agrid(SEQ / 128, NUM_HEADS, BATCH);  // (16, 16, 2)
    flash_attn<<<agrid, 128>>>(gQ, gK, gV, gO);

    sgemm_bias<<<ggrid, gblock>>>(gO, Wo, bo, (float*)d_out);
}

// round 2
// speedup vs baseline: 1.0506x; 1.0506x over previous
#include <cuda_runtime.h>
#include <cuda_bf16.h>

#define D_MODEL 1024
#define NUM_HEADS 16
#define DEPTH 64
#define BATCH 2
#define SEQ 2048
#define MROWS (BATCH * SEQ)   // 4096

typedef unsigned long long u64;

// Scratch (no allocations allowed)
__device__ float g_Q[MROWS * D_MODEL];
__device__ float g_K[MROWS * D_MODEL];
__device__ float g_V[MROWS * D_MODEL];
__device__ float g_O[MROWS * D_MODEL];

// ---------------- packed f32x2 helpers (sm_103a FFMA2 path) ----------------
__device__ __forceinline__ u64 pack2(float x, float y) {
    u64 r;
    asm("mov.b64 %0, {%1, %2};" : "=l"(r) : "f"(x), "f"(y));
    return r;
}
__device__ __forceinline__ u64 fma2(u64 a, u64 b, u64 c) {
    u64 d;
    asm("fma.rn.f32x2 %0, %1, %2, %3;" : "=l"(d) : "l"(a), "l"(b), "l"(c));
    return d;
}
__device__ __forceinline__ u64 add2(u64 a, u64 b) {
    u64 d;
    asm("add.rn.f32x2 %0, %1, %2;" : "=l"(d) : "l"(a), "l"(b));
    return d;
}
__device__ __forceinline__ u64 mul2(u64 a, u64 b) {
    u64 d;
    asm("mul.rn.f32x2 %0, %1, %2;" : "=l"(d) : "l"(a), "l"(b));
    return d;
}
__device__ __forceinline__ void unpack2(u64 v, float& x, float& y) {
    asm("mov.b64 {%0, %1}, %2;" : "=f"(x), "=f"(y) : "l"(v));
}

// ---------------------------------------------------------------------------
// Fused SGEMM: C[M,N] = A[M,K] @ B[K,N] + bias[N], selected by blockIdx.z.
// M=4096, N=K=1024. 128x128x8 tile, 256 threads, 8x8 per-thread micro-tile,
// accumulated as 8x4 packed f32x2.
// ---------------------------------------------------------------------------
__global__ __launch_bounds__(256, 2)
void sgemm_bias3(const float* __restrict__ A0, const float* __restrict__ W0,
                 const float* __restrict__ b0, float* __restrict__ C0,
                 const float* __restrict__ A1, const float* __restrict__ W1,
                 const float* __restrict__ b1, float* __restrict__ C1,
                 const float* __restrict__ A2, const float* __restrict__ W2,
                 const float* __restrict__ b2, float* __restrict__ C2) {
    const int N = 1024, K = 1024;
    const int BM = 128, BN = 128, BK = 8;
    __shared__ __align__(16) float As[BK][BM];
    __shared__ __align__(16) float Bs[BK][BN];

    int z = blockIdx.z;
    const float* A   = (z == 0) ? A0 : (z == 1) ? A1 : A2;
    const float* Bm  = (z == 0) ? W0 : (z == 1) ? W1 : W2;
    const float* bias= (z == 0) ? b0 : (z == 1) ? b1 : b2;
    float* C         = (z == 0) ? C0 : (z == 1) ? C1 : C2;

    int tid = threadIdx.x;
    int tx = tid & 15;        // 0..15  (N direction)
    int ty = tid >> 4;        // 0..15  (M direction)
    int row0 = blockIdx.y * BM;
    int col0 = blockIdx.x * BN;

    u64 acc2[8][4];
#pragma unroll
    for (int i = 0; i < 8; i++)
#pragma unroll
        for (int j = 0; j < 4; j++) acc2[i][j] = 0ULL;

    int arow = tid >> 1;           // 0..127
    int acol = (tid & 1) * 4;      // 0 or 4
    int brow = tid >> 5;           // 0..7
    int bcol = (tid & 31) * 4;     // 0..124

    const float* Ap = A + (size_t)(row0 + arow) * K + acol;
    const float* Bp = Bm + (size_t)brow * N + col0 + bcol;

    for (int k0 = 0; k0 < K; k0 += BK) {
        float4 a4 = *(const float4*)(Ap + k0);
        As[acol + 0][arow] = a4.x;
        As[acol + 1][arow] = a4.y;
        As[acol + 2][arow] = a4.z;
        As[acol + 3][arow] = a4.w;
        float4 b4 = *(const float4*)(Bp + (size_t)k0 * N);
        *(float4*)(&Bs[brow][bcol]) = b4;
        __syncthreads();

#pragma unroll
        for (int kk = 0; kk < BK; kk++) {
            float4 a0 = *(const float4*)(&As[kk][ty * 4]);
            float4 a1 = *(const float4*)(&As[kk][64 + ty * 4]);
            ulonglong2 bl0 = *(const ulonglong2*)(&Bs[kk][tx * 4]);
            ulonglong2 bl1 = *(const ulonglong2*)(&Bs[kk][64 + tx * 4]);
            u64 br2[4] = {bl0.x, bl0.y, bl1.x, bl1.y};
            float ar[8] = {a0.x, a0.y, a0.z, a0.w, a1.x, a1.y, a1.z, a1.w};
#pragma unroll
            for (int i = 0; i < 8; i++) {
                u64 ai = pack2(ar[i], ar[i]);
#pragma unroll
                for (int j = 0; j < 4; j++)
                    acc2[i][j] = fma2(ai, br2[j], acc2[i][j]);
            }
        }
        __syncthreads();
    }

#pragma unroll
    for (int ih = 0; ih < 2; ih++) {
#pragma unroll
        for (int i = 0; i < 4; i++) {
            int r = row0 + ih * 64 + ty * 4 + i;
#pragma unroll
            for (int jh = 0; jh < 2; jh++) {
                int c = col0 + jh * 64 + tx * 4;
                float4 bv = *(const float4*)(bias + c);
                float x0, x1, x2, x3;
                unpack2(acc2[ih * 4 + i][jh * 2 + 0], x0, x1);
                unpack2(acc2[ih * 4 + i][jh * 2 + 1], x2, x3);
                float4 o;
                o.x = x0 + bv.x;
                o.y = x1 + bv.y;
                o.z = x2 + bv.z;
                o.w = x3 + bv.w;
                *(float4*)(C + (size_t)r * N + c) = o;
            }
        }
    }
}

// ---------------------------------------------------------------------------
// Flash attention (causal), fp32 packed-pair math. One thread = one query row.
// Block: 128 threads = 128 queries of one (b,h). K/V staged in 64x64 SMEM tiles.
// ---------------------------------------------------------------------------
__global__ __launch_bounds__(128, 3)
void flash_attn(const float* __restrict__ Q, const float* __restrict__ K,
                const float* __restrict__ V, float* __restrict__ O) {
    __shared__ __align__(16) float Ks[64][64];
    __shared__ __align__(16) float Vs[64][64];

    int qt = blockIdx.x;   // 0..15 (query tile of 128)
    int h  = blockIdx.y;   // 0..15
    int b  = blockIdx.z;   // 0..1
    int tid = threadIdx.x;
    int qi = qt * 128 + tid;

    // Load q, pre-scaled by 1/sqrt(DEPTH)=0.125, as 32 packed pairs.
    const float* qptr = Q + ((size_t)b * SEQ + qi) * D_MODEL + h * DEPTH;
    u64 qp[32];
#pragma unroll
    for (int f = 0; f < 16; f++) {
        float4 t = *(const float4*)(qptr + f * 4);
        qp[2 * f + 0] = pack2(t.x * 0.125f, t.y * 0.125f);
        qp[2 * f + 1] = pack2(t.z * 0.125f, t.w * 0.125f);
    }

    float m = -1e30f, l = 0.f;
    u64 acc[32];
#pragma unroll
    for (int d = 0; d < 32; d++) acc[d] = 0ULL;

    int warp_qmax = qt * 128 + (tid | 31);   // max query index in this warp
    int ktiles = qt * 2 + 2;                 // 64-key tiles covering [0, qi]
    for (int kt = 0; kt < ktiles; kt++) {
        const float* kbase = K + ((size_t)b * SEQ + kt * 64) * D_MODEL + h * DEPTH;
        const float* vbase = V + ((size_t)b * SEQ + kt * 64) * D_MODEL + h * DEPTH;
#pragma unroll
        for (int it = 0; it < 8; it++) {
            int idx = (it * 128 + tid) * 4;
            int r = idx >> 6;
            int c = idx & 63;
            *(float4*)(&Ks[r][c]) = *(const float4*)(kbase + (size_t)r * D_MODEL + c);
            *(float4*)(&Vs[r][c]) = *(const float4*)(vbase + (size_t)r * D_MODEL + c);
        }
        __syncthreads();

        int kmaxw = warp_qmax - kt * 64 + 1;   // warp-uniform trip count
        if (kmaxw > 64) kmaxw = 64;
        int mykm = qi - kt * 64;               // per-thread causal bound (kk <= mykm)

        for (int kk = 0; kk < kmaxw; kk++) {
            const ulonglong2* kr = (const ulonglong2*)(&Ks[kk][0]);
            u64 s0 = 0ULL, s1 = 0ULL, s2 = 0ULL, s3 = 0ULL;
#pragma unroll
            for (int t = 0; t < 16; t += 2) {
                ulonglong2 k0 = kr[t];
                ulonglong2 k1 = kr[t + 1];
                s0 = fma2(qp[2 * t + 0], k0.x, s0);
                s1 = fma2(qp[2 * t + 1], k0.y, s1);
                s2 = fma2(qp[2 * t + 2], k1.x, s2);
                s3 = fma2(qp[2 * t + 3], k1.y, s3);
            }
            u64 sred = add2(add2(s0, s1), add2(s2, s3));
            float slo, shi;
            unpack2(sred, slo, shi);
            float s = slo + shi;
            if (kk > mykm) s = -1e30f;         // causal mask -> p == 0

            if (s > m) {                        // lazy rescale
                float corr = __expf(m - s);
                u64 c2 = pack2(corr, corr);
                l *= corr;
#pragma unroll
                for (int d = 0; d < 32; d++) acc[d] = mul2(acc[d], c2);
                m = s;
            }
            float p = __expf(s - m);
            l += p;
            u64 p2 = pack2(p, p);
            const ulonglong2* vr = (const ulonglong2*)(&Vs[kk][0]);
#pragma unroll
            for (int t = 0; t < 16; t++) {
                ulonglong2 vv = vr[t];
                acc[2 * t + 0] = fma2(p2, vv.x, acc[2 * t + 0]);
                acc[2 * t + 1] = fma2(p2, vv.y, acc[2 * t + 1]);
            }
        }
        __syncthreads();
    }

    float inv = 1.f / l;
    float* optr = O + ((size_t)b * SEQ + qi) * D_MODEL + h * DEPTH;
#pragma unroll
    for (int f = 0; f < 16; f++) {
        float o0, o1, o2, o3;
        unpack2(acc[2 * f + 0], o0, o1);
        unpack2(acc[2 * f + 1], o2, o3);
        float4 o;
        o.x = o0 * inv; o.y = o1 * inv; o.z = o2 * inv; o.w = o3 * inv;
        *(float4*)(optr + f * 4) = o;
    }
}

// ---------------------------------------------------------------------------
// Single-output GEMM for the final projection.
// ---------------------------------------------------------------------------
extern "C" void kernel_launch(void* const* d_in, const int* in_sizes, int n_in,
                              void* d_out, int out_size) {
    const float* v  = (const float*)d_in[0];
    const float* k  = (const float*)d_in[1];
    const float* q  = (const float*)d_in[2];
    // d_in[3] = mask: fixed causal triu * (-1e9); handled analytically.
    const float* Wq = (const float*)d_in[4];
    const float* bq = (const float*)d_in[5];
    const float* Wk = (const float*)d_in[6];
    const float* bk = (const float*)d_in[7];
    const float* Wv = (const float*)d_in[8];
    const float* bv = (const float*)d_in[9];
    const float* Wo = (const float*)d_in[10];
    const float* bo = (const float*)d_in[11];

    float *gQ, *gK, *gV, *gO;
    cudaGetSymbolAddress((void**)&gQ, g_Q);
    cudaGetSymbolAddress((void**)&gK, g_K);
    cudaGetSymbolAddress((void**)&gV, g_V);
    cudaGetSymbolAddress((void**)&gO, g_O);

    dim3 gblock(256);

    // Fused Q/K/V projections: one launch, 768 blocks.
    dim3 qkvgrid(D_MODEL / 128, MROWS / 128, 3);
    sgemm_bias3<<<qkvgrid, gblock>>>(q, Wq, bq, gQ,
                                     k, Wk, bk, gK,
                                     v, Wv, bv, gV);

    dim3 agrid(SEQ / 128, NUM_HEADS, BATCH);  // (16, 16, 2)
    flash_attn<<<agrid, 128>>>(gQ, gK, gV, gO);

    // Output projection straight into d_out (reuse the 3-way kernel, z=1 grid).
    dim3 ogrid(D_MODEL / 128, MROWS / 128, 1);
    sgemm_bias3<<<ogrid, gblock>>>(gO, Wo, bo, (float*)d_out,
                                   gO, Wo, bo, (float*)d_out,
                                   gO, Wo, bo, (float*)d_out);
}